// round 15
// baseline (speedup 1.0000x reference)
#include <cuda_runtime.h>
#include <cuda_bf16.h>
#include <cstdint>

#define L_DIM 131072
#define CSZ   128
#define NCH   (L_DIM / CSZ)     // 1024

// stage: Ahi 4K | Alo 4K | Bhi 4K | Blo 4K  (BM=128, BN=128, BK=16; 32B rows)
#define STAGE_BYTES 16384
#define NSTAGE 6
#define PF 5
#define ZST 132
#define SEG_OFF 67584
#define SMEM_TOTAL (NSTAGE * STAGE_BYTES)   // 98304; zs/seg overlap stages

// ---------------- static device scratch ------------------------------------
__device__ float g_S[(size_t)L_DIM * 512];            // fp32 local-scan states (permuted cols)
__device__ __nv_bfloat16 g_Shi[(size_t)L_DIM * 512];  // corrected split planes
__device__ __nv_bfloat16 g_Slo[(size_t)L_DIM * 512];
__device__ __nv_bfloat16 g_xhi[(size_t)L_DIM * 256];  // pre-split x
__device__ __nv_bfloat16 g_xlo[(size_t)L_DIM * 256];
__device__ float g_gamma[256];
__device__ float g_pow_re[129 * 256];
__device__ float g_pow_im[129 * 256];
__device__ float g_cpow_re[10 * 256];
__device__ float g_cpow_im[10 * 256];
__device__ float g_qr[129 * 512];                     // permuted correction tables
__device__ float g_qi[129 * 512];
__device__ float2 g_ccar[NCH * 256];
__device__ float g_carP_re[NCH * 512];
__device__ float g_carP_im[NCH * 512];
__device__ __nv_bfloat16 g_B2hi[512 * 256];           // rows: tile t (64ch): [re | im], x gamma
__device__ __nv_bfloat16 g_B2lo[512 * 256];
__device__ __nv_bfloat16 g_C2hi[256 * 512];           // row h, permuted k cols
__device__ __nv_bfloat16 g_C2lo[256 * 512];

// ---------------- helpers ---------------------------------------------------
__device__ __forceinline__ uint32_t smem_u32(const void* p) {
    return (uint32_t)__cvta_generic_to_shared(p);
}
__device__ __forceinline__ void ldsm4(uint32_t& r0, uint32_t& r1, uint32_t& r2, uint32_t& r3, uint32_t a) {
    asm volatile("ldmatrix.sync.aligned.m8n8.x4.shared.b16 {%0,%1,%2,%3}, [%4];"
                 : "=r"(r0), "=r"(r1), "=r"(r2), "=r"(r3) : "r"(a));
}
__device__ __forceinline__ void mma_bf16(float* c, const uint32_t* a, const uint32_t* b) {
    asm volatile("mma.sync.aligned.m16n8k16.row.col.f32.bf16.bf16.f32 "
                 "{%0,%1,%2,%3},{%4,%5,%6,%7},{%8,%9},{%0,%1,%2,%3};"
                 : "+f"(c[0]), "+f"(c[1]), "+f"(c[2]), "+f"(c[3])
                 : "r"(a[0]), "r"(a[1]), "r"(a[2]), "r"(a[3]), "r"(b[0]), "r"(b[1]));
}
#define CP_ASYNC(dst, src) asm volatile("cp.async.cg.shared.global [%0], [%1], 16;" :: "r"(dst), "l"(src))
#define CP_COMMIT()        asm volatile("cp.async.commit_group;" ::: "memory")
#define CP_WAIT4()         asm volatile("cp.async.wait_group 4;" ::: "memory")

__device__ __forceinline__ void split2(float v, __nv_bfloat16& h, __nv_bfloat16& l) {
    h = __float2bfloat16(v);
    l = __float2bfloat16(v - __bfloat162float(h));
}
__device__ __forceinline__ uint32_t pack_hi2(float a, float b) {
    __nv_bfloat16 ha = __float2bfloat16(a), hb = __float2bfloat16(b);
    return (uint32_t)__bfloat16_as_ushort(ha) | ((uint32_t)__bfloat16_as_ushort(hb) << 16);
}
__device__ __forceinline__ uint32_t pack_lo2(float a, float b) {
    __nv_bfloat16 ha = __float2bfloat16(a), hb = __float2bfloat16(b);
    __nv_bfloat16 la = __float2bfloat16(a - __bfloat162float(ha));
    __nv_bfloat16 lb = __float2bfloat16(b - __bfloat162float(hb));
    return (uint32_t)__bfloat16_as_ushort(la) | ((uint32_t)__bfloat16_as_ushort(lb) << 16);
}

// ---------------- K0: parameters + tables (64-channel grouping) --------------
__global__ void k_setup(const float* __restrict__ nu_log,
                        const float* __restrict__ theta_log,
                        const float* __restrict__ gamma_log)
{
    int n = threadIdx.x;
    double nu  = exp((double)nu_log[n]);
    double th  = exp((double)theta_log[n]);
    double mag = exp(-nu);
    double lr  = mag * cos(th);
    double li  = mag * sin(th);
    g_gamma[n] = expf(gamma_log[n]);
    int colre = ((n >> 6) << 7) + (n & 63);
    int colim = colre + 64;
    double pr = 1.0, pi = 0.0, cr = 1.0, ci = 0.0;
    for (int p = 0; p <= 128; p++) {
        g_pow_re[p * 256 + n] = (float)pr;
        g_pow_im[p * 256 + n] = (float)pi;
        g_qr[p * 512 + colre] = (float)pr;
        g_qi[p * 512 + colre] = (float)(-pi);
        g_qr[p * 512 + colim] = (float)pi;
        g_qi[p * 512 + colim] = (float)pr;
        if (p == 128) { cr = pr; ci = pi; }
        double t = pr * lr - pi * li;
        pi = pr * li + pi * lr;
        pr = t;
    }
    for (int d = 0; d < 10; d++) {
        g_cpow_re[d * 256 + n] = (float)cr;
        g_cpow_im[d * 256 + n] = (float)ci;
        double t = cr * cr - ci * ci;
        ci = 2.0 * cr * ci;
        cr = t;
    }
}

// ---------------- K0b: pack B and C (64-channel grouping) --------------------
__global__ void k_pack(const float* __restrict__ Bre, const float* __restrict__ Bim,
                       const float* __restrict__ Cre, const float* __restrict__ Cim)
{
    int b = blockIdx.x;
    int t = threadIdx.x;
    if (b < 512) {
        int tile = b >> 7, loc = b & 127;
        int isim = loc >> 6;
        int ch = tile * 64 + (loc & 63);
        const float* src = isim ? Bim : Bre;
        float v = src[ch * 256 + t] * g_gamma[ch];
        __nv_bfloat16 h, l; split2(v, h, l);
        g_B2hi[b * 256 + t] = h;
        g_B2lo[b * 256 + t] = l;
    } else {
        int h = b - 512;
        for (int k = t; k < 512; k += 256) {
            int tile = k >> 7, loc = k & 127;
            int isim = loc >> 6;
            int ch = tile * 64 + (loc & 63);
            float v = isim ? -Cim[h * 256 + ch] : Cre[h * 256 + ch];
            __nv_bfloat16 hh, ll; split2(v, hh, ll);
            g_C2hi[h * 512 + k] = hh;
            g_C2lo[h * 512 + k] = ll;
        }
    }
}

// ---------------- K0c: pre-split x ------------------------------------------
__global__ __launch_bounds__(256) void k_prex(const float* __restrict__ x)
{
    size_t idx = ((size_t)blockIdx.x * 256 + threadIdx.x) * 4;
    float4 v = *(const float4*)(x + idx);
    uint2 hh = make_uint2(pack_hi2(v.x, v.y), pack_hi2(v.z, v.w));
    uint2 ll = make_uint2(pack_lo2(v.x, v.y), pack_lo2(v.z, v.w));
    *(uint2*)&g_xhi[idx] = hh;
    *(uint2*)&g_xlo[idx] = ll;
}

// ---------------- MMA stage: BM=128 BN=128 BK=16, 8 warps of 64x32 -----------
// stage layout: Ahi @0, Alo @4096, Bhi @8192, Blo @12288; rows are 32B.
// swizzle: off(r, g) = r*32 + ((g ^ ((r>>2)&1)) << 4), g in {0,1}
__device__ __forceinline__ void mma_stage(const char* base, float (*acc)[4][4],
                                          int lane, int warpm, int warpn)
{
    const int half = lane >> 4;
    const int l15 = lane & 15;
    uint32_t bh[2][4], bl[2][4];
#pragma unroll
    for (int nb = 0; nb < 2; nb++) {
        int brow = warpn * 32 + nb * 16 + l15;
        int g = half ^ ((brow >> 2) & 1);
        uint32_t bAddr = smem_u32(base + 8192 + brow * 32 + (g << 4));
        ldsm4(bh[nb][0], bh[nb][1], bh[nb][2], bh[nb][3], bAddr);
        ldsm4(bl[nb][0], bl[nb][1], bl[nb][2], bl[nb][3], bAddr + 4096);
    }
#pragma unroll
    for (int mi = 0; mi < 4; mi++) {
        int arow = warpm * 64 + mi * 16 + l15;
        int g = half ^ ((arow >> 2) & 1);
        uint32_t aAddr = smem_u32(base + arow * 32 + (g << 4));
        uint32_t ah[4], al[4];
        ldsm4(ah[0], ah[1], ah[2], ah[3], aAddr);
        ldsm4(al[0], al[1], al[2], al[3], aAddr + 4096);
#pragma unroll
        for (int nb = 0; nb < 2; nb++) {
            uint32_t p0[2] = {bh[nb][0], bh[nb][2]}, p1[2] = {bh[nb][1], bh[nb][3]};
            uint32_t q0[2] = {bl[nb][0], bl[nb][2]}, q1[2] = {bl[nb][1], bl[nb][3]};
            mma_bf16(acc[mi][2 * nb],     ah, p0);
            mma_bf16(acc[mi][2 * nb + 1], ah, p1);
            mma_bf16(acc[mi][2 * nb],     ah, q0);
            mma_bf16(acc[mi][2 * nb + 1], ah, q1);
            mma_bf16(acc[mi][2 * nb],     al, p0);
            mma_bf16(acc[mi][2 * nb + 1], al, p1);
        }
    }
}

__device__ __forceinline__ void acc_to_zs(float* zs, float (*acc)[4][4],
                                          int lane, int warpm, int warpn)
{
#pragma unroll
    for (int mi = 0; mi < 4; mi++)
#pragma unroll
        for (int ni = 0; ni < 4; ni++) {
            int r0 = warpm * 64 + mi * 16 + (lane >> 2);
            int col = warpn * 32 + ni * 8 + (lane & 3) * 2;
            zs[r0 * ZST + col]           = acc[mi][ni][0];
            zs[r0 * ZST + col + 1]       = acc[mi][ni][1];
            zs[(r0 + 8) * ZST + col]     = acc[mi][ni][2];
            zs[(r0 + 8) * ZST + col + 1] = acc[mi][ni][3];
        }
}

// ---------------- K1: Bu GEMM + fused local scan -----------------------------
__global__ __launch_bounds__(256, 2) void k_gemm1()
{
    extern __shared__ __align__(1024) char smem[];
    const int tid  = threadIdx.x;
    const int lane = tid & 31;
    const int warp = tid >> 5;
    const int warpm = warp & 1;         // 2 x 64 rows
    const int warpn = warp >> 1;        // 4 x 32 cols
    const int bx = blockIdx.x;          // 0..3 (64 complex channels each)
    const int by = blockIdx.y;
    const int rowBase = by * CSZ;
    const uint32_t sm0 = smem_u32(smem);

    float acc[4][4][4];
#pragma unroll
    for (int mi = 0; mi < 4; mi++)
#pragma unroll
        for (int ni = 0; ni < 4; ni++)
#pragma unroll
            for (int j = 0; j < 4; j++) acc[mi][ni][j] = 0.f;

    const int rT = tid >> 1;            // 0..127
    const int gT = tid & 1;
    const uint32_t offT = rT * 32 + ((gT ^ ((rT >> 2) & 1)) << 4);
    const __nv_bfloat16* axh = g_xhi + (size_t)(rowBase + rT) * 256 + gT * 8;
    const __nv_bfloat16* axl = g_xlo + (size_t)(rowBase + rT) * 256 + gT * 8;
    const __nv_bfloat16* abh = g_B2hi + (size_t)(bx * 128 + rT) * 256 + gT * 8;
    const __nv_bfloat16* abl = g_B2lo + (size_t)(bx * 128 + rT) * 256 + gT * 8;

    int sNext = 0;
    auto issue = [&]() {
        uint32_t sb = sm0 + sNext * STAGE_BYTES;
        CP_ASYNC(sb + offT,          axh);
        CP_ASYNC(sb + 4096 + offT,   axl);
        CP_ASYNC(sb + 8192 + offT,   abh);
        CP_ASYNC(sb + 12288 + offT,  abl);
        CP_COMMIT();
        axh += 16; axl += 16; abh += 16; abl += 16;
        sNext = (sNext == NSTAGE - 1) ? 0 : sNext + 1;
    };

#pragma unroll
    for (int i = 0; i < PF; i++) issue();
    const int NCC = 16;
    int sCur = 0;
    for (int c = 0; c < NCC; c++) {
        CP_WAIT4();
        __syncthreads();
        if (c + PF < NCC) issue(); else CP_COMMIT();
        mma_stage(smem + sCur * STAGE_BYTES, acc, lane, warpm, warpn);
        sCur = (sCur == NSTAGE - 1) ? 0 : sCur + 1;
    }
    __syncthreads();

    float* zs = (float*)smem;
    acc_to_zs(zs, acc, lane, warpm, warpn);
    __syncthreads();

    // fused local scan: 64 channels x 4 segments x 32 rows
    {
        const int ch  = tid & 63;
        const int seg = tid >> 6;
        const int chg = bx * 64 + ch;
        const float lr = g_pow_re[256 + chg], li = g_pow_im[256 + chg];

        float cr = 0.f, ci = 0.f;
#pragma unroll
        for (int i = 0; i < 32; i++) {
            int r = seg * 32 + i;
            float br = zs[r * ZST + ch];
            float bi = zs[r * ZST + 64 + ch];
            float t = fmaf(lr, cr, fmaf(-li, ci, br));
            ci      = fmaf(lr, ci, fmaf( li, cr, bi));
            cr = t;
        }
        float2* se = (float2*)(smem + SEG_OFF);
        se[seg * 64 + ch] = make_float2(cr, ci);
        __syncthreads();

        const float p32r = g_pow_re[32 * 256 + chg], p32i = g_pow_im[32 * 256 + chg];
        float gr = 0.f, gi = 0.f;
        for (int j = 0; j < seg; j++) {
            float2 e = se[j * 64 + ch];
            float t = fmaf(p32r, gr, fmaf(-p32i, gi, e.x));
            gi      = fmaf(p32r, gi, fmaf( p32i, gr, e.y));
            gr = t;
        }

        float wr = gr, wi = gi;
#pragma unroll
        for (int i = 0; i < 32; i++) {
            int r = seg * 32 + i;
            float br = zs[r * ZST + ch];
            float bi = zs[r * ZST + 64 + ch];
            float t = fmaf(lr, wr, fmaf(-li, wi, br));
            wi      = fmaf(lr, wi, fmaf( li, wr, bi));
            wr = t;
            size_t off = (size_t)(rowBase + r) * 512 + bx * 128;
            g_S[off + ch]      = wr;
            g_S[off + 64 + ch] = wi;
            if (seg == 3 && i == 31) g_ccar[by * 256 + chg] = make_float2(wr, wi);
        }
    }
}

// ---------------- K2: parallel carry scan ------------------------------------
__global__ __launch_bounds__(512) void k_carry()
{
    __shared__ float2 s[NCH];
    const int ch = blockIdx.x;
    const int t = threadIdx.x;
    s[t]       = g_ccar[t * 256 + ch];
    s[t + 512] = g_ccar[(t + 512) * 256 + ch];
    __syncthreads();
#pragma unroll
    for (int d = 0; d < 10; d++) {
        int st = 1 << d;
        float pr = g_cpow_re[d * 256 + ch];
        float pi = g_cpow_im[d * 256 + ch];
        int c0 = t, c1 = t + 512;
        float2 v0 = s[c0], v1 = s[c1];
        if (c0 >= st) {
            float2 w = s[c0 - st];
            v0.x = fmaf(pr, w.x, fmaf(-pi, w.y, v0.x));
            v0.y = fmaf(pr, w.y, fmaf( pi, w.x, v0.y));
        }
        {
            float2 w = s[c1 - st];
            v1.x = fmaf(pr, w.x, fmaf(-pi, w.y, v1.x));
            v1.y = fmaf(pr, w.y, fmaf( pi, w.x, v1.y));
        }
        __syncthreads();
        s[c0] = v0; s[c1] = v1;
        __syncthreads();
    }
    const int colre = ((ch >> 6) << 7) + (ch & 63);
    const int colim = colre + 64;
    float2 e0 = (t == 0) ? make_float2(0.f, 0.f) : s[t - 1];
    g_carP_re[t * 512 + colre] = e0.x;  g_carP_re[t * 512 + colim] = e0.x;
    g_carP_im[t * 512 + colre] = e0.y;  g_carP_im[t * 512 + colim] = e0.y;
    float2 e1 = s[t + 511];
    size_t o1 = (size_t)(t + 512) * 512;
    g_carP_re[o1 + colre] = e1.x;  g_carP_re[o1 + colim] = e1.x;
    g_carP_im[o1 + colre] = e1.y;  g_carP_im[o1 + colim] = e1.y;
}

// ---------------- K2b: correction + split pass -------------------------------
__global__ __launch_bounds__(512) void k_corr()
{
    const int chunk = blockIdx.x;
    const int tid = threadIdx.x;
    const int col = (tid & 255) * 2;
    const int rh  = tid >> 8;
    const int rowBase = chunk * CSZ;
    float2 cr = *(const float2*)&g_carP_re[(size_t)chunk * 512 + col];
    float2 ci = *(const float2*)&g_carP_im[(size_t)chunk * 512 + col];
#pragma unroll 4
    for (int i = 0; i < 64; i++) {
        int r = rh * 64 + i;
        size_t off = (size_t)(rowBase + r) * 512 + col;
        float2 s  = *(const float2*)&g_S[off];
        float2 qr = *(const float2*)&g_qr[(r + 1) * 512 + col];
        float2 qi = *(const float2*)&g_qi[(r + 1) * 512 + col];
        float v0 = s.x + qr.x * cr.x + qi.x * ci.x;
        float v1 = s.y + qr.y * cr.y + qi.y * ci.y;
        *(uint32_t*)&g_Shi[off] = pack_hi2(v0, v1);
        *(uint32_t*)&g_Slo[off] = pack_lo2(v0, v1);
    }
}

// ---------------- K3: output GEMM --------------------------------------------
__global__ __launch_bounds__(256, 2) void k_gemm2(const float* __restrict__ x,
                                                  const float* __restrict__ Dv,
                                                  float* __restrict__ out)
{
    extern __shared__ __align__(1024) char smem[];
    const int tid  = threadIdx.x;
    const int lane = tid & 31;
    const int warp = tid >> 5;
    const int warpm = warp & 1;
    const int warpn = warp >> 1;
    const int bx = blockIdx.x;          // 0..1 h tile
    const int by = blockIdx.y;
    const int rowBase = by * CSZ;
    const uint32_t sm0 = smem_u32(smem);

    float acc[4][4][4];
#pragma unroll
    for (int mi = 0; mi < 4; mi++)
#pragma unroll
        for (int ni = 0; ni < 4; ni++)
#pragma unroll
            for (int j = 0; j < 4; j++) acc[mi][ni][j] = 0.f;

    const int rT = tid >> 1;
    const int gT = tid & 1;
    const uint32_t offT = rT * 32 + ((gT ^ ((rT >> 2) & 1)) << 4);
    const __nv_bfloat16* ash = g_Shi + (size_t)(rowBase + rT) * 512 + gT * 8;
    const __nv_bfloat16* asl = g_Slo + (size_t)(rowBase + rT) * 512 + gT * 8;
    const __nv_bfloat16* abh = g_C2hi + (size_t)(bx * 128 + rT) * 512 + gT * 8;
    const __nv_bfloat16* abl = g_C2lo + (size_t)(bx * 128 + rT) * 512 + gT * 8;

    int sNext = 0;
    auto issue = [&]() {
        uint32_t sb = sm0 + sNext * STAGE_BYTES;
        CP_ASYNC(sb + offT,          ash);
        CP_ASYNC(sb + 4096 + offT,   asl);
        CP_ASYNC(sb + 8192 + offT,   abh);
        CP_ASYNC(sb + 12288 + offT,  abl);
        CP_COMMIT();
        ash += 16; asl += 16; abh += 16; abl += 16;
        sNext = (sNext == NSTAGE - 1) ? 0 : sNext + 1;
    };

#pragma unroll
    for (int i = 0; i < PF; i++) issue();
    const int NCC = 32;
    int sCur = 0;
    for (int c = 0; c < NCC; c++) {
        CP_WAIT4();
        __syncthreads();
        if (c + PF < NCC) issue(); else CP_COMMIT();
        mma_stage(smem + sCur * STAGE_BYTES, acc, lane, warpm, warpn);
        sCur = (sCur == NSTAGE - 1) ? 0 : sCur + 1;
    }
    __syncthreads();

    float* zs = (float*)smem;
    acc_to_zs(zs, acc, lane, warpm, warpn);
    __syncthreads();

    // epilogue: y = zs + D*x   (128 cols per CTA)
    {
        int col = (tid & 31) * 4;
        int gh = bx * 128 + col;
        float4 dv = *(const float4*)&Dv[gh];
#pragma unroll
        for (int i = 0; i < 16; i++) {
            int r = (tid >> 5) + 8 * i;
            size_t l = (size_t)(rowBase + r);
            float4 xv = *(const float4*)&x[l * 256 + gh];
            float4 o;
            o.x = zs[r * ZST + col + 0] + dv.x * xv.x;
            o.y = zs[r * ZST + col + 1] + dv.y * xv.y;
            o.z = zs[r * ZST + col + 2] + dv.z * xv.z;
            o.w = zs[r * ZST + col + 3] + dv.w * xv.w;
            *(float4*)(out + l * 256 + gh) = o;
        }
    }
}

// ---------------- launch ----------------------------------------------------
extern "C" void kernel_launch(void* const* d_in, const int* in_sizes, int n_in,
                              void* d_out, int out_size)
{
    const float* x         = (const float*)d_in[0];
    const float* nu_log    = (const float*)d_in[1];
    const float* theta_log = (const float*)d_in[2];
    const float* B_re      = (const float*)d_in[3];
    const float* B_im      = (const float*)d_in[4];
    const float* C_re      = (const float*)d_in[5];
    const float* C_im      = (const float*)d_in[6];
    const float* Dv        = (const float*)d_in[7];
    const float* gamma_log = (const float*)d_in[8];
    float* out = (float*)d_out;

    cudaFuncSetAttribute(k_gemm1, cudaFuncAttributeMaxDynamicSharedMemorySize, SMEM_TOTAL);
    cudaFuncSetAttribute(k_gemm2, cudaFuncAttributeMaxDynamicSharedMemorySize, SMEM_TOTAL);

    k_setup<<<1, 256>>>(nu_log, theta_log, gamma_log);
    k_pack<<<768, 256>>>(B_re, B_im, C_re, C_im);
    k_prex<<<L_DIM * 256 / 1024, 256>>>(x);
    k_gemm1<<<dim3(4, 1024), 256, SMEM_TOTAL>>>();
    k_carry<<<256, 512>>>();
    k_corr<<<1024, 512>>>();
    k_gemm2<<<dim3(2, 1024), 256, SMEM_TOTAL>>>(x, Dv, out);
}

// round 16
// speedup vs baseline: 1.0284x; 1.0284x over previous
#include <cuda_runtime.h>
#include <cuda_bf16.h>
#include <cstdint>

#define L_DIM 131072
#define CSZ   128
#define NCH   (L_DIM / CSZ)     // 1024

// stage: Ahi 8K | Alo 8K | Bhi 8K | Blo 8K  (BM=128, BN=128, BK=32; 64B rows)
#define STAGE_BYTES 32768
#define NSTAGE 5
#define BAR_OFF (NSTAGE * STAGE_BYTES)      // 163840
#define SMEM_TOTAL (BAR_OFF + 256)
#define ZST 132
#define SEG_OFF 67584
#define NTHREADS 384                        // 8 consumer warps + 4 producer warps

// ---------------- static device scratch ------------------------------------
__device__ float g_S[(size_t)L_DIM * 512];            // fp32 local-scan states (permuted cols)
__device__ __nv_bfloat16 g_Shi[(size_t)L_DIM * 512];  // corrected split planes
__device__ __nv_bfloat16 g_Slo[(size_t)L_DIM * 512];
__device__ __nv_bfloat16 g_xhi[(size_t)L_DIM * 256];  // pre-split x
__device__ __nv_bfloat16 g_xlo[(size_t)L_DIM * 256];
__device__ float g_gamma[256];
__device__ float g_pow_re[129 * 256];
__device__ float g_pow_im[129 * 256];
__device__ float g_cpow_re[10 * 256];
__device__ float g_cpow_im[10 * 256];
__device__ float g_qr[129 * 512];                     // permuted correction tables
__device__ float g_qi[129 * 512];
__device__ float2 g_ccar[NCH * 256];
__device__ float g_carP_re[NCH * 512];
__device__ float g_carP_im[NCH * 512];
__device__ __nv_bfloat16 g_B2hi[512 * 256];           // rows: tile t (64ch): [re | im], x gamma
__device__ __nv_bfloat16 g_B2lo[512 * 256];
__device__ __nv_bfloat16 g_C2hi[256 * 512];           // row h, permuted k cols
__device__ __nv_bfloat16 g_C2lo[256 * 512];

// ---------------- helpers ---------------------------------------------------
__device__ __forceinline__ uint32_t smem_u32(const void* p) {
    return (uint32_t)__cvta_generic_to_shared(p);
}
__device__ __forceinline__ void ldsm4(uint32_t& r0, uint32_t& r1, uint32_t& r2, uint32_t& r3, uint32_t a) {
    asm volatile("ldmatrix.sync.aligned.m8n8.x4.shared.b16 {%0,%1,%2,%3}, [%4];"
                 : "=r"(r0), "=r"(r1), "=r"(r2), "=r"(r3) : "r"(a));
}
__device__ __forceinline__ void mma_bf16(float* c, const uint32_t* a, const uint32_t* b) {
    asm volatile("mma.sync.aligned.m16n8k16.row.col.f32.bf16.bf16.f32 "
                 "{%0,%1,%2,%3},{%4,%5,%6,%7},{%8,%9},{%0,%1,%2,%3};"
                 : "+f"(c[0]), "+f"(c[1]), "+f"(c[2]), "+f"(c[3])
                 : "r"(a[0]), "r"(a[1]), "r"(a[2]), "r"(a[3]), "r"(b[0]), "r"(b[1]));
}
#define CP_ASYNC(dst, src) asm volatile("cp.async.cg.shared.global [%0], [%1], 16;" :: "r"(dst), "l"(src))
#define CPA_MBAR_ARRIVE(mb) asm volatile("cp.async.mbarrier.arrive.noinc.shared::cta.b64 [%0];" :: "r"(mb) : "memory")
#define MBAR_INIT(mb, c) asm volatile("mbarrier.init.shared.b64 [%0], %1;" :: "r"(mb), "r"(c) : "memory")
#define MBAR_ARRIVE(mb)  asm volatile("mbarrier.arrive.shared.b64 _, [%0];" :: "r"(mb) : "memory")
__device__ __forceinline__ void mbar_wait(uint32_t mb, uint32_t parity) {
    asm volatile(
        "{\n\t.reg .pred P1;\n\t"
        "W_%=:\n\t"
        "mbarrier.try_wait.parity.acquire.cta.shared::cta.b64 P1, [%0], %1, 0x989680;\n\t"
        "@P1 bra.uni D_%=;\n\t"
        "bra.uni W_%=;\n\t"
        "D_%=:\n\t}"
        :: "r"(mb), "r"(parity) : "memory");
}

__device__ __forceinline__ void split2(float v, __nv_bfloat16& h, __nv_bfloat16& l) {
    h = __float2bfloat16(v);
    l = __float2bfloat16(v - __bfloat162float(h));
}
__device__ __forceinline__ uint32_t pack_hi2(float a, float b) {
    __nv_bfloat16 ha = __float2bfloat16(a), hb = __float2bfloat16(b);
    return (uint32_t)__bfloat16_as_ushort(ha) | ((uint32_t)__bfloat16_as_ushort(hb) << 16);
}
__device__ __forceinline__ uint32_t pack_lo2(float a, float b) {
    __nv_bfloat16 ha = __float2bfloat16(a), hb = __float2bfloat16(b);
    __nv_bfloat16 la = __float2bfloat16(a - __bfloat162float(ha));
    __nv_bfloat16 lb = __float2bfloat16(b - __bfloat162float(hb));
    return (uint32_t)__bfloat16_as_ushort(la) | ((uint32_t)__bfloat16_as_ushort(lb) << 16);
}

// ---------------- K0: parameters + tables (64-channel grouping) --------------
__global__ void k_setup(const float* __restrict__ nu_log,
                        const float* __restrict__ theta_log,
                        const float* __restrict__ gamma_log)
{
    int n = threadIdx.x;
    double nu  = exp((double)nu_log[n]);
    double th  = exp((double)theta_log[n]);
    double mag = exp(-nu);
    double lr  = mag * cos(th);
    double li  = mag * sin(th);
    g_gamma[n] = expf(gamma_log[n]);
    int colre = ((n >> 6) << 7) + (n & 63);
    int colim = colre + 64;
    double pr = 1.0, pi = 0.0, cr = 1.0, ci = 0.0;
    for (int p = 0; p <= 128; p++) {
        g_pow_re[p * 256 + n] = (float)pr;
        g_pow_im[p * 256 + n] = (float)pi;
        g_qr[p * 512 + colre] = (float)pr;
        g_qi[p * 512 + colre] = (float)(-pi);
        g_qr[p * 512 + colim] = (float)pi;
        g_qi[p * 512 + colim] = (float)pr;
        if (p == 128) { cr = pr; ci = pi; }
        double t = pr * lr - pi * li;
        pi = pr * li + pi * lr;
        pr = t;
    }
    for (int d = 0; d < 10; d++) {
        g_cpow_re[d * 256 + n] = (float)cr;
        g_cpow_im[d * 256 + n] = (float)ci;
        double t = cr * cr - ci * ci;
        ci = 2.0 * cr * ci;
        cr = t;
    }
}

// ---------------- K0b: pack B and C (64-channel grouping) --------------------
__global__ void k_pack(const float* __restrict__ Bre, const float* __restrict__ Bim,
                       const float* __restrict__ Cre, const float* __restrict__ Cim)
{
    int b = blockIdx.x;
    int t = threadIdx.x;
    if (b < 512) {
        int tile = b >> 7, loc = b & 127;
        int isim = loc >> 6;
        int ch = tile * 64 + (loc & 63);
        const float* src = isim ? Bim : Bre;
        float v = src[ch * 256 + t] * g_gamma[ch];
        __nv_bfloat16 h, l; split2(v, h, l);
        g_B2hi[b * 256 + t] = h;
        g_B2lo[b * 256 + t] = l;
    } else {
        int h = b - 512;
        for (int k = t; k < 512; k += 256) {
            int tile = k >> 7, loc = k & 127;
            int isim = loc >> 6;
            int ch = tile * 64 + (loc & 63);
            float v = isim ? -Cim[h * 256 + ch] : Cre[h * 256 + ch];
            __nv_bfloat16 hh, ll; split2(v, hh, ll);
            g_C2hi[h * 512 + k] = hh;
            g_C2lo[h * 512 + k] = ll;
        }
    }
}

// ---------------- K0c: pre-split x ------------------------------------------
__global__ __launch_bounds__(256) void k_prex(const float* __restrict__ x)
{
    size_t idx = ((size_t)blockIdx.x * 256 + threadIdx.x) * 4;
    float4 v = *(const float4*)(x + idx);
    uint2 hh = make_uint2(pack_hi2(v.x, v.y), pack_hi2(v.z, v.w));
    uint2 ll = make_uint2(pack_lo2(v.x, v.y), pack_lo2(v.z, v.w));
    *(uint2*)&g_xhi[idx] = hh;
    *(uint2*)&g_xlo[idx] = ll;
}

// ---------------- MMA stage: BM=128 BN=128 BK=32, 8 warps of 64x32 -----------
// stage layout: Ahi @0, Alo @8192, Bhi @16384, Blo @24576; rows are 64B.
// swizzle: off(r, g) = r*64 + ((g ^ ((r>>1)&3)) << 4)
__device__ __forceinline__ void mma_stage(const char* base, float (*acc)[4][4],
                                          int lane, int warpm, int warpn)
{
    const int half = lane >> 4;
    const int l15 = lane & 15;
#pragma unroll
    for (int ks = 0; ks < 2; ks++) {
        uint32_t bh[2][4], bl[2][4];
#pragma unroll
        for (int nb = 0; nb < 2; nb++) {
            int brow = warpn * 32 + nb * 16 + l15;
            int colB = (ks * 2 + half) ^ ((brow >> 1) & 3);
            uint32_t bAddr = smem_u32(base + 16384 + brow * 64 + (colB << 4));
            ldsm4(bh[nb][0], bh[nb][1], bh[nb][2], bh[nb][3], bAddr);
            ldsm4(bl[nb][0], bl[nb][1], bl[nb][2], bl[nb][3], bAddr + 8192);
        }
#pragma unroll
        for (int mi = 0; mi < 4; mi++) {
            int arow = warpm * 64 + mi * 16 + l15;
            int colA = (ks * 2 + half) ^ ((arow >> 1) & 3);
            uint32_t aAddr = smem_u32(base + arow * 64 + (colA << 4));
            uint32_t ah[4], al[4];
            ldsm4(ah[0], ah[1], ah[2], ah[3], aAddr);
            ldsm4(al[0], al[1], al[2], al[3], aAddr + 8192);
#pragma unroll
            for (int nb = 0; nb < 2; nb++) {
                uint32_t p0[2] = {bh[nb][0], bh[nb][2]}, p1[2] = {bh[nb][1], bh[nb][3]};
                uint32_t q0[2] = {bl[nb][0], bl[nb][2]}, q1[2] = {bl[nb][1], bl[nb][3]};
                mma_bf16(acc[mi][2 * nb],     ah, p0);
                mma_bf16(acc[mi][2 * nb + 1], ah, p1);
                mma_bf16(acc[mi][2 * nb],     ah, q0);
                mma_bf16(acc[mi][2 * nb + 1], ah, q1);
                mma_bf16(acc[mi][2 * nb],     al, p0);
                mma_bf16(acc[mi][2 * nb + 1], al, p1);
            }
        }
    }
}

__device__ __forceinline__ void acc_to_zs(float* zs, float (*acc)[4][4],
                                          int lane, int warpm, int warpn)
{
#pragma unroll
    for (int mi = 0; mi < 4; mi++)
#pragma unroll
        for (int ni = 0; ni < 4; ni++) {
            int r0 = warpm * 64 + mi * 16 + (lane >> 2);
            int col = warpn * 32 + ni * 8 + (lane & 3) * 2;
            zs[r0 * ZST + col]           = acc[mi][ni][0];
            zs[r0 * ZST + col + 1]       = acc[mi][ni][1];
            zs[(r0 + 8) * ZST + col]     = acc[mi][ni][2];
            zs[(r0 + 8) * ZST + col + 1] = acc[mi][ni][3];
        }
}

// ---------------- K1: Bu GEMM (warp-specialized) + fused local scan ----------
__global__ __launch_bounds__(NTHREADS, 1) void k_gemm1()
{
    extern __shared__ __align__(1024) char smem[];
    const int tid  = threadIdx.x;
    const int lane = tid & 31;
    const int warp = tid >> 5;
    const int bx = blockIdx.x;          // 0..3 (64 complex channels each)
    const int by = blockIdx.y;
    const int rowBase = by * CSZ;
    const uint32_t sm0 = smem_u32(smem);

    if (tid == 0) {
#pragma unroll
        for (int s = 0; s < NSTAGE; s++) {
            MBAR_INIT(sm0 + BAR_OFF + s * 16, 128);      // full: 4 producer warps
            MBAR_INIT(sm0 + BAR_OFF + s * 16 + 8, 256);  // empty: 8 consumer warps
        }
    }
    __syncthreads();

    const int NCC = 8;
    float acc[4][4][4];

    if (warp >= 8) {
        // ---- producers ----
        const int ptid = tid - 256;     // 0..127
        uint32_t soff[4]; uint32_t goff[4];
#pragma unroll
        for (int j = 0; j < 4; j++) {
            int ck = j * 128 + ptid;
            int r = ck >> 2, g = ck & 3;
            soff[j] = r * 64 + ((g ^ ((r >> 1) & 3)) << 4);
            goff[j] = r * 256 + g * 8;
        }
        const __nv_bfloat16* axh = g_xhi  + (size_t)rowBase * 256;
        const __nv_bfloat16* axl = g_xlo  + (size_t)rowBase * 256;
        const __nv_bfloat16* abh = g_B2hi + (size_t)(bx * 128) * 256;
        const __nv_bfloat16* abl = g_B2lo + (size_t)(bx * 128) * 256;
        int stage = 0, phase = 1;
        for (int c = 0; c < NCC; c++) {
            uint32_t fb = sm0 + BAR_OFF + stage * 16;
            mbar_wait(fb + 8, phase);
            uint32_t sb = sm0 + stage * STAGE_BYTES;
#pragma unroll
            for (int j = 0; j < 4; j++) {
                CP_ASYNC(sb + soff[j],          axh + goff[j]);
                CP_ASYNC(sb + 8192 + soff[j],   axl + goff[j]);
                CP_ASYNC(sb + 16384 + soff[j],  abh + goff[j]);
                CP_ASYNC(sb + 24576 + soff[j],  abl + goff[j]);
            }
            CPA_MBAR_ARRIVE(fb);
            axh += 32; axl += 32; abh += 32; abl += 32;
            if (++stage == NSTAGE) { stage = 0; phase ^= 1; }
        }
    } else {
        // ---- consumers ----
        const int warpm = warp & 1;
        const int warpn = warp >> 1;
#pragma unroll
        for (int mi = 0; mi < 4; mi++)
#pragma unroll
            for (int ni = 0; ni < 4; ni++)
#pragma unroll
                for (int j = 0; j < 4; j++) acc[mi][ni][j] = 0.f;
        int stage = 0, phase = 0;
        for (int c = 0; c < NCC; c++) {
            uint32_t fb = sm0 + BAR_OFF + stage * 16;
            mbar_wait(fb, phase);
            mma_stage(smem + stage * STAGE_BYTES, acc, lane, warpm, warpn);
            MBAR_ARRIVE(fb + 8);
            if (++stage == NSTAGE) { stage = 0; phase ^= 1; }
        }
    }
    __syncthreads();

    float* zs = (float*)smem;
    if (warp < 8) {
        const int warpm = warp & 1;
        const int warpn = warp >> 1;
        acc_to_zs(zs, acc, lane, warpm, warpn);
    }
    __syncthreads();

    // ---- fused local scan: 64 channels x 4 segments x 32 rows (256 threads) --
    {
        const int ch  = tid & 63;
        const int seg = (tid >> 6) & 3;
        const int chg = bx * 64 + ch;
        const float lr = g_pow_re[256 + chg], li = g_pow_im[256 + chg];
        float2* se = (float2*)(smem + SEG_OFF);
        float cr = 0.f, ci = 0.f;

        if (tid < 256) {
#pragma unroll
            for (int i = 0; i < 32; i++) {
                int r = seg * 32 + i;
                float br = zs[r * ZST + ch];
                float bi = zs[r * ZST + 64 + ch];
                float t = fmaf(lr, cr, fmaf(-li, ci, br));
                ci      = fmaf(lr, ci, fmaf( li, cr, bi));
                cr = t;
            }
            se[seg * 64 + ch] = make_float2(cr, ci);
        }
        __syncthreads();

        if (tid < 256) {
            const float p32r = g_pow_re[32 * 256 + chg], p32i = g_pow_im[32 * 256 + chg];
            float gr = 0.f, gi = 0.f;
            for (int j = 0; j < seg; j++) {
                float2 e = se[j * 64 + ch];
                float t = fmaf(p32r, gr, fmaf(-p32i, gi, e.x));
                gi      = fmaf(p32r, gi, fmaf( p32i, gr, e.y));
                gr = t;
            }
            float wr = gr, wi = gi;
#pragma unroll
            for (int i = 0; i < 32; i++) {
                int r = seg * 32 + i;
                float br = zs[r * ZST + ch];
                float bi = zs[r * ZST + 64 + ch];
                float t = fmaf(lr, wr, fmaf(-li, wi, br));
                wi      = fmaf(lr, wi, fmaf( li, wr, bi));
                wr = t;
                size_t off = (size_t)(rowBase + r) * 512 + bx * 128;
                g_S[off + ch]      = wr;
                g_S[off + 64 + ch] = wi;
                if (seg == 3 && i == 31) g_ccar[by * 256 + chg] = make_float2(wr, wi);
            }
        }
    }
}

// ---------------- K2: parallel carry scan ------------------------------------
__global__ __launch_bounds__(512) void k_carry()
{
    __shared__ float2 s[NCH];
    const int ch = blockIdx.x;
    const int t = threadIdx.x;
    s[t]       = g_ccar[t * 256 + ch];
    s[t + 512] = g_ccar[(t + 512) * 256 + ch];
    __syncthreads();
#pragma unroll
    for (int d = 0; d < 10; d++) {
        int st = 1 << d;
        float pr = g_cpow_re[d * 256 + ch];
        float pi = g_cpow_im[d * 256 + ch];
        int c0 = t, c1 = t + 512;
        float2 v0 = s[c0], v1 = s[c1];
        if (c0 >= st) {
            float2 w = s[c0 - st];
            v0.x = fmaf(pr, w.x, fmaf(-pi, w.y, v0.x));
            v0.y = fmaf(pr, w.y, fmaf( pi, w.x, v0.y));
        }
        {
            float2 w = s[c1 - st];
            v1.x = fmaf(pr, w.x, fmaf(-pi, w.y, v1.x));
            v1.y = fmaf(pr, w.y, fmaf( pi, w.x, v1.y));
        }
        __syncthreads();
        s[c0] = v0; s[c1] = v1;
        __syncthreads();
    }
    const int colre = ((ch >> 6) << 7) + (ch & 63);
    const int colim = colre + 64;
    float2 e0 = (t == 0) ? make_float2(0.f, 0.f) : s[t - 1];
    g_carP_re[t * 512 + colre] = e0.x;  g_carP_re[t * 512 + colim] = e0.x;
    g_carP_im[t * 512 + colre] = e0.y;  g_carP_im[t * 512 + colim] = e0.y;
    float2 e1 = s[t + 511];
    size_t o1 = (size_t)(t + 512) * 512;
    g_carP_re[o1 + colre] = e1.x;  g_carP_re[o1 + colim] = e1.x;
    g_carP_im[o1 + colre] = e1.y;  g_carP_im[o1 + colim] = e1.y;
}

// ---------------- K2b: correction + split pass -------------------------------
__global__ __launch_bounds__(512) void k_corr()
{
    const int chunk = blockIdx.x;
    const int tid = threadIdx.x;
    const int col = (tid & 255) * 2;
    const int rh  = tid >> 8;
    const int rowBase = chunk * CSZ;
    float2 cr = *(const float2*)&g_carP_re[(size_t)chunk * 512 + col];
    float2 ci = *(const float2*)&g_carP_im[(size_t)chunk * 512 + col];
#pragma unroll 4
    for (int i = 0; i < 64; i++) {
        int r = rh * 64 + i;
        size_t off = (size_t)(rowBase + r) * 512 + col;
        float2 s  = *(const float2*)&g_S[off];
        float2 qr = *(const float2*)&g_qr[(r + 1) * 512 + col];
        float2 qi = *(const float2*)&g_qi[(r + 1) * 512 + col];
        float v0 = s.x + qr.x * cr.x + qi.x * ci.x;
        float v1 = s.y + qr.y * cr.y + qi.y * ci.y;
        *(uint32_t*)&g_Shi[off] = pack_hi2(v0, v1);
        *(uint32_t*)&g_Slo[off] = pack_lo2(v0, v1);
    }
}

// ---------------- K3: output GEMM (warp-specialized) -------------------------
__global__ __launch_bounds__(NTHREADS, 1) void k_gemm2(const float* __restrict__ x,
                                                       const float* __restrict__ Dv,
                                                       float* __restrict__ out)
{
    extern __shared__ __align__(1024) char smem[];
    const int tid  = threadIdx.x;
    const int lane = tid & 31;
    const int warp = tid >> 5;
    const int bx = blockIdx.x;          // 0..1 h tile
    const int by = blockIdx.y;
    const int rowBase = by * CSZ;
    const uint32_t sm0 = smem_u32(smem);

    if (tid == 0) {
#pragma unroll
        for (int s = 0; s < NSTAGE; s++) {
            MBAR_INIT(sm0 + BAR_OFF + s * 16, 128);
            MBAR_INIT(sm0 + BAR_OFF + s * 16 + 8, 256);
        }
    }
    __syncthreads();

    const int NCC = 16;
    float acc[4][4][4];

    if (warp >= 8) {
        const int ptid = tid - 256;
        uint32_t soff[4]; uint32_t goff[4];
#pragma unroll
        for (int j = 0; j < 4; j++) {
            int ck = j * 128 + ptid;
            int r = ck >> 2, g = ck & 3;
            soff[j] = r * 64 + ((g ^ ((r >> 1) & 3)) << 4);
            goff[j] = r * 512 + g * 8;
        }
        const __nv_bfloat16* ash = g_Shi + (size_t)rowBase * 512;
        const __nv_bfloat16* asl = g_Slo + (size_t)rowBase * 512;
        const __nv_bfloat16* abh = g_C2hi + (size_t)(bx * 128) * 512;
        const __nv_bfloat16* abl = g_C2lo + (size_t)(bx * 128) * 512;
        int stage = 0, phase = 1;
        for (int c = 0; c < NCC; c++) {
            uint32_t fb = sm0 + BAR_OFF + stage * 16;
            mbar_wait(fb + 8, phase);
            uint32_t sb = sm0 + stage * STAGE_BYTES;
#pragma unroll
            for (int j = 0; j < 4; j++) {
                CP_ASYNC(sb + soff[j],          ash + goff[j]);
                CP_ASYNC(sb + 8192 + soff[j],   asl + goff[j]);
                CP_ASYNC(sb + 16384 + soff[j],  abh + goff[j]);
                CP_ASYNC(sb + 24576 + soff[j],  abl + goff[j]);
            }
            CPA_MBAR_ARRIVE(fb);
            ash += 32; asl += 32; abh += 32; abl += 32;
            if (++stage == NSTAGE) { stage = 0; phase ^= 1; }
        }
    } else {
        const int warpm = warp & 1;
        const int warpn = warp >> 1;
#pragma unroll
        for (int mi = 0; mi < 4; mi++)
#pragma unroll
            for (int ni = 0; ni < 4; ni++)
#pragma unroll
                for (int j = 0; j < 4; j++) acc[mi][ni][j] = 0.f;
        int stage = 0, phase = 0;
        for (int c = 0; c < NCC; c++) {
            uint32_t fb = sm0 + BAR_OFF + stage * 16;
            mbar_wait(fb, phase);
            mma_stage(smem + stage * STAGE_BYTES, acc, lane, warpm, warpn);
            MBAR_ARRIVE(fb + 8);
            if (++stage == NSTAGE) { stage = 0; phase ^= 1; }
        }
    }
    __syncthreads();

    float* zs = (float*)smem;
    if (warp < 8) {
        const int warpm = warp & 1;
        const int warpn = warp >> 1;
        acc_to_zs(zs, acc, lane, warpm, warpn);
    }
    __syncthreads();

    // epilogue: y = zs + D*x   (128 cols per CTA; 256 threads)
    if (tid < 256) {
        int col = (tid & 31) * 4;
        int gh = bx * 128 + col;
        float4 dv = *(const float4*)&Dv[gh];
#pragma unroll
        for (int i = 0; i < 16; i++) {
            int r = (tid >> 5) + 8 * i;
            size_t l = (size_t)(rowBase + r);
            float4 xv = *(const float4*)&x[l * 256 + gh];
            float4 o;
            o.x = zs[r * ZST + col + 0] + dv.x * xv.x;
            o.y = zs[r * ZST + col + 1] + dv.y * xv.y;
            o.z = zs[r * ZST + col + 2] + dv.z * xv.z;
            o.w = zs[r * ZST + col + 3] + dv.w * xv.w;
            *(float4*)(out + l * 256 + gh) = o;
        }
    }
}

// ---------------- launch ----------------------------------------------------
extern "C" void kernel_launch(void* const* d_in, const int* in_sizes, int n_in,
                              void* d_out, int out_size)
{
    const float* x         = (const float*)d_in[0];
    const float* nu_log    = (const float*)d_in[1];
    const float* theta_log = (const float*)d_in[2];
    const float* B_re      = (const float*)d_in[3];
    const float* B_im      = (const float*)d_in[4];
    const float* C_re      = (const float*)d_in[5];
    const float* C_im      = (const float*)d_in[6];
    const float* Dv        = (const float*)d_in[7];
    const float* gamma_log = (const float*)d_in[8];
    float* out = (float*)d_out;

    cudaFuncSetAttribute(k_gemm1, cudaFuncAttributeMaxDynamicSharedMemorySize, SMEM_TOTAL);
    cudaFuncSetAttribute(k_gemm2, cudaFuncAttributeMaxDynamicSharedMemorySize, SMEM_TOTAL);

    k_setup<<<1, 256>>>(nu_log, theta_log, gamma_log);
    k_pack<<<768, 256>>>(B_re, B_im, C_re, C_im);
    k_prex<<<L_DIM * 256 / 1024, 256>>>(x);
    k_gemm1<<<dim3(4, 1024), NTHREADS, SMEM_TOTAL>>>();
    k_carry<<<256, 512>>>();
    k_corr<<<1024, 512>>>();
    k_gemm2<<<dim3(2, 1024), NTHREADS, SMEM_TOTAL>>>(x, Dv, out);
}

// round 17
// speedup vs baseline: 1.4978x; 1.4564x over previous
#include <cuda_runtime.h>
#include <cuda_fp16.h>
#include <cstdint>

#define L_DIM 131072
#define CSZ   128
#define NCH   (L_DIM / CSZ)     // 1024

// stage: Ah 8K | Bh 8K | Bl 8K  (BM=128, BN=128, BK=32; 64B rows, fp16)
#define STAGE_BYTES 24576
#define NSTAGE 3
#define ZST 132
#define SEG_OFF 67584
#define SMEM_TOTAL (NSTAGE * STAGE_BYTES)   // 73728; zs/seg overlap stages

// ---------------- static device scratch ------------------------------------
__device__ float g_S[(size_t)L_DIM * 512];            // fp32 local-scan states (permuted cols)
__device__ __half g_Sh[(size_t)L_DIM * 512];          // corrected states, single fp16 plane
__device__ __half g_xh[(size_t)L_DIM * 256];          // x, single fp16 plane
__device__ float g_gamma[256];
__device__ float g_pow_re[129 * 256];
__device__ float g_pow_im[129 * 256];
__device__ float g_cpow_re[10 * 256];
__device__ float g_cpow_im[10 * 256];
__device__ float g_qr[129 * 512];                     // permuted correction tables
__device__ float g_qi[129 * 512];
__device__ float2 g_ccar[NCH * 256];
__device__ float g_carP_re[NCH * 512];
__device__ float g_carP_im[NCH * 512];
__device__ __half g_B2h[512 * 256];                   // rows: tile t (64ch): [re | im], x gamma
__device__ __half g_B2l[512 * 256];
__device__ __half g_C2h[256 * 512];                   // row h, permuted k cols
__device__ __half g_C2l[256 * 512];

// ---------------- helpers ---------------------------------------------------
__device__ __forceinline__ uint32_t smem_u32(const void* p) {
    return (uint32_t)__cvta_generic_to_shared(p);
}
__device__ __forceinline__ void ldsm4(uint32_t& r0, uint32_t& r1, uint32_t& r2, uint32_t& r3, uint32_t a) {
    asm volatile("ldmatrix.sync.aligned.m8n8.x4.shared.b16 {%0,%1,%2,%3}, [%4];"
                 : "=r"(r0), "=r"(r1), "=r"(r2), "=r"(r3) : "r"(a));
}
__device__ __forceinline__ void mma_f16(float* c, const uint32_t* a, const uint32_t* b) {
    asm volatile("mma.sync.aligned.m16n8k16.row.col.f32.f16.f16.f32 "
                 "{%0,%1,%2,%3},{%4,%5,%6,%7},{%8,%9},{%0,%1,%2,%3};"
                 : "+f"(c[0]), "+f"(c[1]), "+f"(c[2]), "+f"(c[3])
                 : "r"(a[0]), "r"(a[1]), "r"(a[2]), "r"(a[3]), "r"(b[0]), "r"(b[1]));
}
#define CP_ASYNC(dst, src) asm volatile("cp.async.cg.shared.global [%0], [%1], 16;" :: "r"(dst), "l"(src))
#define CP_COMMIT()        asm volatile("cp.async.commit_group;" ::: "memory")
#define CP_WAIT0()         asm volatile("cp.async.wait_group 0;" ::: "memory")
#define CP_WAIT1()         asm volatile("cp.async.wait_group 1;" ::: "memory")

__device__ __forceinline__ void splitH(float v, __half& h, __half& l) {
    h = __float2half_rn(v);
    l = __float2half_rn(v - __half2float(h));
}

// ---------------- K0: parameters + tables (64-channel grouping) --------------
__global__ void k_setup(const float* __restrict__ nu_log,
                        const float* __restrict__ theta_log,
                        const float* __restrict__ gamma_log)
{
    int n = threadIdx.x;
    double nu  = exp((double)nu_log[n]);
    double th  = exp((double)theta_log[n]);
    double mag = exp(-nu);
    double lr  = mag * cos(th);
    double li  = mag * sin(th);
    g_gamma[n] = expf(gamma_log[n]);
    int colre = ((n >> 6) << 7) + (n & 63);
    int colim = colre + 64;
    double pr = 1.0, pi = 0.0, cr = 1.0, ci = 0.0;
    for (int p = 0; p <= 128; p++) {
        g_pow_re[p * 256 + n] = (float)pr;
        g_pow_im[p * 256 + n] = (float)pi;
        g_qr[p * 512 + colre] = (float)pr;
        g_qi[p * 512 + colre] = (float)(-pi);
        g_qr[p * 512 + colim] = (float)pi;
        g_qi[p * 512 + colim] = (float)pr;
        if (p == 128) { cr = pr; ci = pi; }
        double t = pr * lr - pi * li;
        pi = pr * li + pi * lr;
        pr = t;
    }
    for (int d = 0; d < 10; d++) {
        g_cpow_re[d * 256 + n] = (float)cr;
        g_cpow_im[d * 256 + n] = (float)ci;
        double t = cr * cr - ci * ci;
        ci = 2.0 * cr * ci;
        cr = t;
    }
}

// ---------------- K0b: pack B and C (fp16 hi/lo planes) ----------------------
__global__ void k_pack(const float* __restrict__ Bre, const float* __restrict__ Bim,
                       const float* __restrict__ Cre, const float* __restrict__ Cim)
{
    int b = blockIdx.x;
    int t = threadIdx.x;
    if (b < 512) {
        int tile = b >> 7, loc = b & 127;
        int isim = loc >> 6;
        int ch = tile * 64 + (loc & 63);
        const float* src = isim ? Bim : Bre;
        float v = src[ch * 256 + t] * g_gamma[ch];
        __half h, l; splitH(v, h, l);
        g_B2h[b * 256 + t] = h;
        g_B2l[b * 256 + t] = l;
    } else {
        int h = b - 512;
        for (int k = t; k < 512; k += 256) {
            int tile = k >> 7, loc = k & 127;
            int isim = loc >> 6;
            int ch = tile * 64 + (loc & 63);
            float v = isim ? -Cim[h * 256 + ch] : Cre[h * 256 + ch];
            __half hh, ll; splitH(v, hh, ll);
            g_C2h[h * 512 + k] = hh;
            g_C2l[h * 512 + k] = ll;
        }
    }
}

// ---------------- K0c: x -> single fp16 plane --------------------------------
__global__ __launch_bounds__(256) void k_prex(const float* __restrict__ x)
{
    size_t idx = ((size_t)blockIdx.x * 256 + threadIdx.x) * 4;
    float4 v = *(const float4*)(x + idx);
    *(__half2*)&g_xh[idx]     = __floats2half2_rn(v.x, v.y);
    *(__half2*)&g_xh[idx + 2] = __floats2half2_rn(v.z, v.w);
}

// ---------------- MMA stage: BM=128 BN=128 BK=32, 8 warps of 64x32, 2-combo --
// stage layout: Ah @0, Bh @8192, Bl @16384; rows are 64B.
// swizzle: off(r, g) = r*64 + ((g ^ ((r>>1)&3)) << 4)
__device__ __forceinline__ void mma_stage(const char* base, float (*acc)[4][4],
                                          int lane, int warpm, int warpn)
{
    const int half = lane >> 4;
    const int l15 = lane & 15;
#pragma unroll
    for (int ks = 0; ks < 2; ks++) {
        uint32_t bh[2][4], bl[2][4];
#pragma unroll
        for (int nb = 0; nb < 2; nb++) {
            int brow = warpn * 32 + nb * 16 + l15;
            int colB = (ks * 2 + half) ^ ((brow >> 1) & 3);
            uint32_t bAddr = smem_u32(base + 8192 + brow * 64 + (colB << 4));
            ldsm4(bh[nb][0], bh[nb][1], bh[nb][2], bh[nb][3], bAddr);
            ldsm4(bl[nb][0], bl[nb][1], bl[nb][2], bl[nb][3], bAddr + 8192);
        }
#pragma unroll
        for (int mi = 0; mi < 4; mi++) {
            int arow = warpm * 64 + mi * 16 + l15;
            int colA = (ks * 2 + half) ^ ((arow >> 1) & 3);
            uint32_t aAddr = smem_u32(base + arow * 64 + (colA << 4));
            uint32_t ah[4];
            ldsm4(ah[0], ah[1], ah[2], ah[3], aAddr);
#pragma unroll
            for (int nb = 0; nb < 2; nb++) {
                uint32_t p0[2] = {bh[nb][0], bh[nb][2]}, p1[2] = {bh[nb][1], bh[nb][3]};
                uint32_t q0[2] = {bl[nb][0], bl[nb][2]}, q1[2] = {bl[nb][1], bl[nb][3]};
                mma_f16(acc[mi][2 * nb],     ah, p0);
                mma_f16(acc[mi][2 * nb + 1], ah, p1);
                mma_f16(acc[mi][2 * nb],     ah, q0);
                mma_f16(acc[mi][2 * nb + 1], ah, q1);
            }
        }
    }
}

__device__ __forceinline__ void acc_to_zs(float* zs, float (*acc)[4][4],
                                          int lane, int warpm, int warpn)
{
#pragma unroll
    for (int mi = 0; mi < 4; mi++)
#pragma unroll
        for (int ni = 0; ni < 4; ni++) {
            int r0 = warpm * 64 + mi * 16 + (lane >> 2);
            int col = warpn * 32 + ni * 8 + (lane & 3) * 2;
            zs[r0 * ZST + col]           = acc[mi][ni][0];
            zs[r0 * ZST + col + 1]       = acc[mi][ni][1];
            zs[(r0 + 8) * ZST + col]     = acc[mi][ni][2];
            zs[(r0 + 8) * ZST + col + 1] = acc[mi][ni][3];
        }
}

// ---------------- K1: Bu GEMM + fused local scan -----------------------------
__global__ __launch_bounds__(256, 2) void k_gemm1()
{
    extern __shared__ __align__(1024) char smem[];
    const int tid  = threadIdx.x;
    const int lane = tid & 31;
    const int warp = tid >> 5;
    const int warpm = warp & 1;         // 2 x 64 rows
    const int warpn = warp >> 1;        // 4 x 32 cols
    const int bx = blockIdx.x;          // 0..3 (64 complex channels each)
    const int by = blockIdx.y;
    const int rowBase = by * CSZ;
    const uint32_t sm0 = smem_u32(smem);

    float acc[4][4][4];
#pragma unroll
    for (int mi = 0; mi < 4; mi++)
#pragma unroll
        for (int ni = 0; ni < 4; ni++)
#pragma unroll
            for (int j = 0; j < 4; j++) acc[mi][ni][j] = 0.f;

    const int rT = tid >> 2;            // 0..63 (rep adds 64)
    const int gT = tid & 3;
    const uint32_t offT = rT * 64 + ((gT ^ ((rT >> 1) & 3)) << 4);
    const __half* axh = g_xh  + (size_t)(rowBase + rT) * 256 + gT * 8;
    const __half* abh = g_B2h + (size_t)(bx * 128 + rT) * 256 + gT * 8;
    const __half* abl = g_B2l + (size_t)(bx * 128 + rT) * 256 + gT * 8;

    int sNext = 0;
    auto issue = [&]() {
        uint32_t sb = sm0 + sNext * STAGE_BYTES;
        CP_ASYNC(sb + offT,                 axh);
        CP_ASYNC(sb + offT + 4096,          axh + 64 * 256);
        CP_ASYNC(sb + 8192 + offT,          abh);
        CP_ASYNC(sb + 8192 + offT + 4096,   abh + 64 * 256);
        CP_ASYNC(sb + 16384 + offT,         abl);
        CP_ASYNC(sb + 16384 + offT + 4096,  abl + 64 * 256);
        CP_COMMIT();
        axh += 32; abh += 32; abl += 32;
        sNext = (sNext == NSTAGE - 1) ? 0 : sNext + 1;
    };

    issue(); issue();
    const int NCC = 8;
    int sCur = 0;
    for (int c = 0; c < NCC; c++) {
        if (c + 1 < NCC) { CP_WAIT1(); } else { CP_WAIT0(); }
        __syncthreads();
        if (c + 2 < NCC) issue();
        mma_stage(smem + sCur * STAGE_BYTES, acc, lane, warpm, warpn);
        sCur = (sCur == NSTAGE - 1) ? 0 : sCur + 1;
    }
    __syncthreads();

    float* zs = (float*)smem;
    acc_to_zs(zs, acc, lane, warpm, warpn);
    __syncthreads();

    // fused local scan: 64 channels x 4 segments x 32 rows
    {
        const int ch  = tid & 63;
        const int seg = tid >> 6;
        const int chg = bx * 64 + ch;
        const float lr = g_pow_re[256 + chg], li = g_pow_im[256 + chg];

        float cr = 0.f, ci = 0.f;
#pragma unroll
        for (int i = 0; i < 32; i++) {
            int r = seg * 32 + i;
            float br = zs[r * ZST + ch];
            float bi = zs[r * ZST + 64 + ch];
            float t = fmaf(lr, cr, fmaf(-li, ci, br));
            ci      = fmaf(lr, ci, fmaf( li, cr, bi));
            cr = t;
        }
        float2* se = (float2*)(smem + SEG_OFF);
        se[seg * 64 + ch] = make_float2(cr, ci);
        __syncthreads();

        const float p32r = g_pow_re[32 * 256 + chg], p32i = g_pow_im[32 * 256 + chg];
        float gr = 0.f, gi = 0.f;
        for (int j = 0; j < seg; j++) {
            float2 e = se[j * 64 + ch];
            float t = fmaf(p32r, gr, fmaf(-p32i, gi, e.x));
            gi      = fmaf(p32r, gi, fmaf( p32i, gr, e.y));
            gr = t;
        }

        float wr = gr, wi = gi;
#pragma unroll
        for (int i = 0; i < 32; i++) {
            int r = seg * 32 + i;
            float br = zs[r * ZST + ch];
            float bi = zs[r * ZST + 64 + ch];
            float t = fmaf(lr, wr, fmaf(-li, wi, br));
            wi      = fmaf(lr, wi, fmaf( li, wr, bi));
            wr = t;
            size_t off = (size_t)(rowBase + r) * 512 + bx * 128;
            g_S[off + ch]      = wr;
            g_S[off + 64 + ch] = wi;
            if (seg == 3 && i == 31) g_ccar[by * 256 + chg] = make_float2(wr, wi);
        }
    }
}

// ---------------- K2: parallel carry scan ------------------------------------
__global__ __launch_bounds__(512) void k_carry()
{
    __shared__ float2 s[NCH];
    const int ch = blockIdx.x;
    const int t = threadIdx.x;
    s[t]       = g_ccar[t * 256 + ch];
    s[t + 512] = g_ccar[(t + 512) * 256 + ch];
    __syncthreads();
#pragma unroll
    for (int d = 0; d < 10; d++) {
        int st = 1 << d;
        float pr = g_cpow_re[d * 256 + ch];
        float pi = g_cpow_im[d * 256 + ch];
        int c0 = t, c1 = t + 512;
        float2 v0 = s[c0], v1 = s[c1];
        if (c0 >= st) {
            float2 w = s[c0 - st];
            v0.x = fmaf(pr, w.x, fmaf(-pi, w.y, v0.x));
            v0.y = fmaf(pr, w.y, fmaf( pi, w.x, v0.y));
        }
        {
            float2 w = s[c1 - st];
            v1.x = fmaf(pr, w.x, fmaf(-pi, w.y, v1.x));
            v1.y = fmaf(pr, w.y, fmaf( pi, w.x, v1.y));
        }
        __syncthreads();
        s[c0] = v0; s[c1] = v1;
        __syncthreads();
    }
    const int colre = ((ch >> 6) << 7) + (ch & 63);
    const int colim = colre + 64;
    float2 e0 = (t == 0) ? make_float2(0.f, 0.f) : s[t - 1];
    g_carP_re[t * 512 + colre] = e0.x;  g_carP_re[t * 512 + colim] = e0.x;
    g_carP_im[t * 512 + colre] = e0.y;  g_carP_im[t * 512 + colim] = e0.y;
    float2 e1 = s[t + 511];
    size_t o1 = (size_t)(t + 512) * 512;
    g_carP_re[o1 + colre] = e1.x;  g_carP_re[o1 + colim] = e1.x;
    g_carP_im[o1 + colre] = e1.y;  g_carP_im[o1 + colim] = e1.y;
}

// ---------------- K2b: correction + fp16 pack pass ---------------------------
__global__ __launch_bounds__(512) void k_corr()
{
    const int chunk = blockIdx.x;
    const int tid = threadIdx.x;
    const int col = (tid & 255) * 2;
    const int rh  = tid >> 8;
    const int rowBase = chunk * CSZ;
    float2 cr = *(const float2*)&g_carP_re[(size_t)chunk * 512 + col];
    float2 ci = *(const float2*)&g_carP_im[(size_t)chunk * 512 + col];
#pragma unroll 4
    for (int i = 0; i < 64; i++) {
        int r = rh * 64 + i;
        size_t off = (size_t)(rowBase + r) * 512 + col;
        float2 s  = *(const float2*)&g_S[off];
        float2 qr = *(const float2*)&g_qr[(r + 1) * 512 + col];
        float2 qi = *(const float2*)&g_qi[(r + 1) * 512 + col];
        float v0 = s.x + qr.x * cr.x + qi.x * ci.x;
        float v1 = s.y + qr.y * cr.y + qi.y * ci.y;
        *(__half2*)&g_Sh[off] = __floats2half2_rn(v0, v1);
    }
}

// ---------------- K3: output GEMM --------------------------------------------
__global__ __launch_bounds__(256, 2) void k_gemm2(const float* __restrict__ x,
                                                  const float* __restrict__ Dv,
                                                  float* __restrict__ out)
{
    extern __shared__ __align__(1024) char smem[];
    const int tid  = threadIdx.x;
    const int lane = tid & 31;
    const int warp = tid >> 5;
    const int warpm = warp & 1;
    const int warpn = warp >> 1;
    const int bx = blockIdx.x;          // 0..1 h tile
    const int by = blockIdx.y;
    const int rowBase = by * CSZ;
    const uint32_t sm0 = smem_u32(smem);

    float acc[4][4][4];
#pragma unroll
    for (int mi = 0; mi < 4; mi++)
#pragma unroll
        for (int ni = 0; ni < 4; ni++)
#pragma unroll
            for (int j = 0; j < 4; j++) acc[mi][ni][j] = 0.f;

    const int rT = tid >> 2;
    const int gT = tid & 3;
    const uint32_t offT = rT * 64 + ((gT ^ ((rT >> 1) & 3)) << 4);
    const __half* ash = g_Sh  + (size_t)(rowBase + rT) * 512 + gT * 8;
    const __half* abh = g_C2h + (size_t)(bx * 128 + rT) * 512 + gT * 8;
    const __half* abl = g_C2l + (size_t)(bx * 128 + rT) * 512 + gT * 8;

    int sNext = 0;
    auto issue = [&]() {
        uint32_t sb = sm0 + sNext * STAGE_BYTES;
        CP_ASYNC(sb + offT,                 ash);
        CP_ASYNC(sb + offT + 4096,          ash + (size_t)64 * 512);
        CP_ASYNC(sb + 8192 + offT,          abh);
        CP_ASYNC(sb + 8192 + offT + 4096,   abh + (size_t)64 * 512);
        CP_ASYNC(sb + 16384 + offT,         abl);
        CP_ASYNC(sb + 16384 + offT + 4096,  abl + (size_t)64 * 512);
        CP_COMMIT();
        ash += 32; abh += 32; abl += 32;
        sNext = (sNext == NSTAGE - 1) ? 0 : sNext + 1;
    };

    issue(); issue();
    const int NCC = 16;
    int sCur = 0;
    for (int c = 0; c < NCC; c++) {
        if (c + 1 < NCC) { CP_WAIT1(); } else { CP_WAIT0(); }
        __syncthreads();
        if (c + 2 < NCC) issue();
        mma_stage(smem + sCur * STAGE_BYTES, acc, lane, warpm, warpn);
        sCur = (sCur == NSTAGE - 1) ? 0 : sCur + 1;
    }
    __syncthreads();

    float* zs = (float*)smem;
    acc_to_zs(zs, acc, lane, warpm, warpn);
    __syncthreads();

    // epilogue: y = zs + D*x   (128 cols per CTA)
    {
        int col = (tid & 31) * 4;
        int gh = bx * 128 + col;
        float4 dv = *(const float4*)&Dv[gh];
#pragma unroll
        for (int i = 0; i < 16; i++) {
            int r = (tid >> 5) + 8 * i;
            size_t l = (size_t)(rowBase + r);
            float4 xv = *(const float4*)&x[l * 256 + gh];
            float4 o;
            o.x = zs[r * ZST + col + 0] + dv.x * xv.x;
            o.y = zs[r * ZST + col + 1] + dv.y * xv.y;
            o.z = zs[r * ZST + col + 2] + dv.z * xv.z;
            o.w = zs[r * ZST + col + 3] + dv.w * xv.w;
            *(float4*)(out + l * 256 + gh) = o;
        }
    }
}

// ---------------- launch ----------------------------------------------------
extern "C" void kernel_launch(void* const* d_in, const int* in_sizes, int n_in,
                              void* d_out, int out_size)
{
    const float* x         = (const float*)d_in[0];
    const float* nu_log    = (const float*)d_in[1];
    const float* theta_log = (const float*)d_in[2];
    const float* B_re      = (const float*)d_in[3];
    const float* B_im      = (const float*)d_in[4];
    const float* C_re      = (const float*)d_in[5];
    const float* C_im      = (const float*)d_in[6];
    const float* Dv        = (const float*)d_in[7];
    const float* gamma_log = (const float*)d_in[8];
    float* out = (float*)d_out;

    cudaFuncSetAttribute(k_gemm1, cudaFuncAttributeMaxDynamicSharedMemorySize, SMEM_TOTAL);
    cudaFuncSetAttribute(k_gemm2, cudaFuncAttributeMaxDynamicSharedMemorySize, SMEM_TOTAL);

    k_setup<<<1, 256>>>(nu_log, theta_log, gamma_log);
    k_pack<<<768, 256>>>(B_re, B_im, C_re, C_im);
    k_prex<<<L_DIM * 256 / 1024, 256>>>(x);
    k_gemm1<<<dim3(4, 1024), 256, SMEM_TOTAL>>>();
    k_carry<<<256, 512>>>();
    k_corr<<<1024, 512>>>();
    k_gemm2<<<dim3(2, 1024), 256, SMEM_TOTAL>>>(x, Dv, out);
}